// round 6
// baseline (speedup 1.0000x reference)
#include <cuda_runtime.h>
#include <math.h>
#include <stdint.h>

#define BB 128
#define SS 200
#define QQ 20000
#define VV 128
#define KK 128
#define CC 64
#define SUMD 128
#define NROWS (BB*SS)

// Interleaved per-(b,s) record: [negE(128) | A(128) | W(64)] = 320 floats
#define STEPF 320
#define CH 50
#define NCH (SS/CH)
#define CHBYTES (CH*STEPF*4)
#define SCAN_SMEM (2*CHBYTES + 16)

// precompute geometry
#define PROWS 64
#define PT 640
#define KCH 16
#define NKCH (KK/KCH)
#define WCH_E (KCH*VV*4)
#define WCH_K (KCH*CC*4)
#define WCH_TOT (2*WCH_E + WCH_K)
#define OFF_QK   (PROWS*KK)
#define OFF_WE   (2*PROWS*KK)
#define OFF_WA   (OFF_WE + 2*KCH*VV)
#define OFF_WK   (OFF_WA + 2*KCH*VV)
#define OFF_MB   (OFF_WK + 2*KCH*CC)
#define PRE_SMEM ((OFF_MB + 4)*4)

__device__ float g_pack[(size_t)NROWS * STEPF];

typedef unsigned long long ull;

__device__ __forceinline__ ull fma2(ull a, ull b, ull c) {
    ull d;
    asm("fma.rn.f32x2 %0, %1, %2, %3;" : "=l"(d) : "l"(a), "l"(b), "l"(c));
    return d;
}
__device__ __forceinline__ ull pack2(float x, float y) {
    ull d;
    asm("mov.b64 %0, {%1, %2};" : "=l"(d) : "f"(x), "f"(y));
    return d;
}
__device__ __forceinline__ float2 unpack2(ull v) {
    float2 r;
    asm("mov.b64 {%0, %1}, %2;" : "=f"(r.x), "=f"(r.y) : "l"(v));
    return r;
}
__device__ __forceinline__ uint32_t smem_u32(const void* p) {
    uint32_t a;
    asm("{ .reg .u64 t; cvta.to.shared.u64 t, %1; cvt.u32.u64 %0, t; }" : "=r"(a) : "l"(p));
    return a;
}
__device__ __forceinline__ void mbar_init(uint32_t mbar, uint32_t cnt) {
    asm volatile("mbarrier.init.shared.b64 [%0], %1;" :: "r"(mbar), "r"(cnt) : "memory");
}
__device__ __forceinline__ void mbar_expect_tx(uint32_t mbar, uint32_t bytes) {
    asm volatile("mbarrier.arrive.expect_tx.shared.b64 _, [%0], %1;" :: "r"(mbar), "r"(bytes) : "memory");
}
__device__ __forceinline__ void mbar_wait(uint32_t mbar, uint32_t parity) {
    asm volatile(
        "{\n\t.reg .pred P;\n"
        "WAITLOOP_%=:\n\t"
        "mbarrier.try_wait.parity.acquire.cta.shared::cta.b64 P, [%0], %1, 0x989680;\n\t"
        "@P bra.uni WAITDONE_%=;\n\t"
        "bra.uni WAITLOOP_%=;\n"
        "WAITDONE_%=:\n\t}"
        :: "r"(mbar), "r"(parity) : "memory");
}
__device__ __forceinline__ void bulk_g2s(uint32_t dst, const void* src, uint32_t bytes, uint32_t mbar) {
    asm volatile(
        "cp.async.bulk.shared::cta.global.mbarrier::complete_tx::bytes [%0], [%1], %2, [%3];"
        :: "r"(dst), "l"(src), "r"(bytes), "r"(mbar) : "memory");
}

// ---------------------------------------------------------------------------
// Kernel A: precompute (register-tiled SGEMM).
// ---------------------------------------------------------------------------
__global__ __launch_bounds__(PT) void precompute_kernel(
    const float* __restrict__ q_emb,
    const float* __restrict__ i_emb,
    const float* __restrict__ key_memory,
    const float* __restrict__ erase_W,
    const float* __restrict__ erase_b,
    const float* __restrict__ add_W,
    const float* __restrict__ add_b,
    const int*   __restrict__ input)
{
    extern __shared__ __align__(16) float psm[];
    float* sIV = psm;
    float* sQK = psm + OFF_QK;
    float* sWE = psm + OFF_WE;
    float* sWA = psm + OFF_WA;
    float* sWK = psm + OFF_WK;
    const uint32_t mb = smem_u32(psm + OFF_MB);

    __shared__ float sLg[PROWS][68];
    __shared__ int   sIdx[PROWS];

    const int t    = threadIdx.x;
    const int lane = t & 31;
    const int wid  = t >> 5;
    const int tc   = t % 80;
    const int tr   = t / 80;
    const int row0 = blockIdx.x * PROWS;

    if (t < PROWS) sIdx[t] = input[row0 + t];
    if (t == 0) {
        mbar_init(mb, 1);
        asm volatile("fence.proxy.async.shared::cta;" ::: "memory");
        mbar_expect_tx(mb, WCH_TOT);
        bulk_g2s(smem_u32(sWE), erase_W,    WCH_E, mb);
        bulk_g2s(smem_u32(sWA), add_W,      WCH_E, mb);
        bulk_g2s(smem_u32(sWK), key_memory, WCH_K, mb);
    }
    __syncthreads();

    for (int r = wid; r < PROWS; r += PT/32) {
        const int idx = sIdx[r];
        const int qid = idx > QQ ? idx - QQ : idx;
        float4 v  = *((const float4*)(i_emb + (size_t)idx * VV) + lane);
        float4 qv = *((const float4*)(q_emb + (size_t)qid * KK) + lane);
        *(float4*)&sIV[r * KK + lane * 4] = v;
        *(float4*)&sQK[r * KK + lane * 4] = qv;
    }
    __syncthreads();

    const float* Asrc = (tc < 64) ? sIV : sQK;
    const float* Wreg;
    int wstride;
    ull bias0, bias1;
    if (tc < 32) {
        Wreg = sWE + tc * 4; wstride = VV;
        float4 b = *(const float4*)(erase_b + tc * 4);
        bias0 = pack2(b.x, b.y); bias1 = pack2(b.z, b.w);
    } else if (tc < 64) {
        Wreg = sWA + (tc - 32) * 4; wstride = VV;
        float4 b = *(const float4*)(add_b + (tc - 32) * 4);
        bias0 = pack2(b.x, b.y); bias1 = pack2(b.z, b.w);
    } else {
        Wreg = sWK + (tc - 64) * 4; wstride = CC;
        bias0 = bias1 = pack2(0.f, 0.f);
    }

    ull acc[8][2];
#pragma unroll
    for (int i = 0; i < 8; i++) { acc[i][0] = bias0; acc[i][1] = bias1; }

    for (int ch = 0; ch < NKCH; ch++) {
        const int buf = ch & 1;
        mbar_wait(mb, ch & 1);
        __syncthreads();
        if (t == 0 && ch + 1 < NKCH) {
            const int nb = buf ^ 1, k0n = (ch + 1) * KCH;
            mbar_expect_tx(mb, WCH_TOT);
            bulk_g2s(smem_u32(sWE + nb * KCH * VV), erase_W    + k0n * VV, WCH_E, mb);
            bulk_g2s(smem_u32(sWA + nb * KCH * VV), add_W      + k0n * VV, WCH_E, mb);
            bulk_g2s(smem_u32(sWK + nb * KCH * CC), key_memory + k0n * CC, WCH_K, mb);
        }

        const float* W = Wreg + buf * KCH * wstride;
        const float* A = Asrc + tr * 8 * KK + ch * KCH;
#pragma unroll
        for (int kk = 0; kk < KCH; kk += 4) {
            ulonglong2 wl[4];
#pragma unroll
            for (int j = 0; j < 4; j++)
                wl[j] = *(const ulonglong2*)(W + (kk + j) * wstride);
            float4 av[8];
#pragma unroll
            for (int i = 0; i < 8; i++)
                av[i] = *(const float4*)(A + i * KK + kk);
#pragma unroll
            for (int j = 0; j < 4; j++) {
#pragma unroll
                for (int i = 0; i < 8; i++) {
                    const float a = ((const float*)&av[i])[j];
                    const ull ad = pack2(a, a);
                    acc[i][0] = fma2(ad, wl[j].x, acc[i][0]);
                    acc[i][1] = fma2(ad, wl[j].y, acc[i][1]);
                }
            }
        }
    }

    if (tc < 32) {
#pragma unroll
        for (int i = 0; i < 8; i++) {
            const int r = row0 + tr * 8 + i;
            float2 f0 = unpack2(acc[i][0]), f1 = unpack2(acc[i][1]);
            float4 o;
            o.x = -1.f / (1.f + __expf(-f0.x));
            o.y = -1.f / (1.f + __expf(-f0.y));
            o.z = -1.f / (1.f + __expf(-f1.x));
            o.w = -1.f / (1.f + __expf(-f1.y));
            *(float4*)&g_pack[(size_t)r * STEPF + tc * 4] = o;
        }
    } else if (tc < 64) {
#pragma unroll
        for (int i = 0; i < 8; i++) {
            const int r = row0 + tr * 8 + i;
            float2 f0 = unpack2(acc[i][0]), f1 = unpack2(acc[i][1]);
            float4 o;
            o.x = tanhf(f0.x); o.y = tanhf(f0.y);
            o.z = tanhf(f1.x); o.w = tanhf(f1.y);
            *(float4*)&g_pack[(size_t)r * STEPF + 128 + (tc - 32) * 4] = o;
        }
    } else {
#pragma unroll
        for (int i = 0; i < 8; i++) {
            float2 f0 = unpack2(acc[i][0]), f1 = unpack2(acc[i][1]);
            float4 o; o.x = f0.x; o.y = f0.y; o.z = f1.x; o.w = f1.y;
            *(float4*)&sLg[tr * 8 + i][(tc - 64) * 4] = o;
        }
    }
    __syncthreads();

    if (t < PROWS) {
        float mx = -1e30f;
#pragma unroll
        for (int c = 0; c < CC; c++) mx = fmaxf(mx, sLg[t][c]);
        float sum = 0.f;
#pragma unroll
        for (int c = 0; c < CC; c++) { float e = __expf(sLg[t][c] - mx); sLg[t][c] = e; sum += e; }
        const float inv = 1.f / sum;
        float* dst = g_pack + (size_t)(row0 + t) * STEPF + 256;
#pragma unroll
        for (int c = 0; c < CC; c++) dst[c] = sLg[t][c] * inv;
    }
}

// ---------------------------------------------------------------------------
// Kernel B: scan + readout. One CTA per batch, 512 threads, 4v x 4c tile.
// Explicit register double-buffer software pipeline; parallel readout.
// ---------------------------------------------------------------------------
__global__ __launch_bounds__(512) void scan_kernel(
    const float* __restrict__ q_emb,
    const float* __restrict__ key_memory,
    const float* __restrict__ init_value_memory,
    const float* __restrict__ summ_W,
    const float* __restrict__ summ_b,
    const float* __restrict__ out_W,
    const float* __restrict__ out_b,
    const int*   __restrict__ target_id,
    float* __restrict__ out)
{
    extern __shared__ __align__(16) float dsm[];
    __shared__ float sQv[KK];
    __shared__ float sWt[CC];
    __shared__ float sCat[VV + KK];
    __shared__ float sPart[8][65];
    __shared__ float sRed[16][132];
    __shared__ float sRed2[4];

    const int b    = blockIdx.x;
    const int t    = threadIdx.x;
    const int lane = t & 31;
    const int wid  = t >> 5;
    const int vg   = t >> 4;    // 0..31 -> v rows [4*vg, 4*vg+4)
    const int cg   = t & 15;    // 0..15 -> c cols [4*cg, 4*cg+4)

    const uint32_t mb0 = smem_u32(dsm + 2 * CH * STEPF);
    const uint32_t mb1 = mb0 + 8;

    if (t == 0) {
        mbar_init(mb0, 1);
        mbar_init(mb1, 1);
        asm volatile("fence.proxy.async.shared::cta;" ::: "memory");
    }
    __syncthreads();

    // m2[q*4+jc] = (mem[vg*4+2q][cg*4+jc], mem[vg*4+2q+1][cg*4+jc])
    ull m2[8];
#pragma unroll
    for (int q = 0; q < 2; q++) {
        const float4 ra = *(const float4*)(init_value_memory + (vg*4 + 2*q    ) * CC + cg*4);
        const float4 rb = *(const float4*)(init_value_memory + (vg*4 + 2*q + 1) * CC + cg*4);
        m2[q*4 + 0] = pack2(ra.x, rb.x);
        m2[q*4 + 1] = pack2(ra.y, rb.y);
        m2[q*4 + 2] = pack2(ra.z, rb.z);
        m2[q*4 + 3] = pack2(ra.w, rb.w);
    }

    const char* gsrc = (const char*)(g_pack + (size_t)b * SS * STEPF);
    if (t == 0) {
        mbar_expect_tx(mb0, CHBYTES);
        bulk_g2s(smem_u32(dsm), gsrc, CHBYTES, mb0);
    }

    ulonglong2 ne[2], aa[2];
    float4 wf[2];

#define LOADSTEP(slot, sp) do { \
        ne[slot] = *(const ulonglong2*)((sp) + vg * 4); \
        aa[slot] = *(const ulonglong2*)((sp) + 128 + vg * 4); \
        wf[slot] = *(const float4*)((sp) + 256 + cg * 4); \
    } while (0)

#define COMPUTE(slot) do { \
        const ull w0 = pack2(wf[slot].x, wf[slot].x); \
        const ull w1 = pack2(wf[slot].y, wf[slot].y); \
        const ull w2 = pack2(wf[slot].z, wf[slot].z); \
        const ull w3 = pack2(wf[slot].w, wf[slot].w); \
        m2[0] = fma2(w0, fma2(m2[0], ne[slot].x, aa[slot].x), m2[0]); \
        m2[1] = fma2(w1, fma2(m2[1], ne[slot].x, aa[slot].x), m2[1]); \
        m2[2] = fma2(w2, fma2(m2[2], ne[slot].x, aa[slot].x), m2[2]); \
        m2[3] = fma2(w3, fma2(m2[3], ne[slot].x, aa[slot].x), m2[3]); \
        m2[4] = fma2(w0, fma2(m2[4], ne[slot].y, aa[slot].y), m2[4]); \
        m2[5] = fma2(w1, fma2(m2[5], ne[slot].y, aa[slot].y), m2[5]); \
        m2[6] = fma2(w2, fma2(m2[6], ne[slot].y, aa[slot].y), m2[6]); \
        m2[7] = fma2(w3, fma2(m2[7], ne[slot].y, aa[slot].y), m2[7]); \
    } while (0)

    int ph0 = 0, ph1 = 0;
    for (int kc = 0; kc < NCH; kc++) {
        const int p = kc & 1;
        if (p == 0) { mbar_wait(mb0, ph0); ph0 ^= 1; }
        else        { mbar_wait(mb1, ph1); ph1 ^= 1; }
        __syncthreads();
        if (t == 0 && kc + 1 < NCH) {
            const uint32_t mbn = (p == 0) ? mb1 : mb0;
            mbar_expect_tx(mbn, CHBYTES);
            bulk_g2s(smem_u32(dsm) + (p ^ 1) * CHBYTES, gsrc + (size_t)(kc + 1) * CHBYTES,
                     CHBYTES, mbn);
        }

        const float* base = dsm + p * CH * STEPF;
        LOADSTEP(0, base);
#pragma unroll 7
        for (int s = 0; s < CH - 1; s++) {
            const int cur = s & 1;
            const float* spn = base + (s + 1) * STEPF;
            LOADSTEP(cur ^ 1, spn);
            COMPUTE(cur);
        }
        COMPUTE((CH - 1) & 1);
    }
#undef LOADSTEP
#undef COMPUTE

    // =============== Parallel readout ===============
    const int tgt = target_id[b];
    if (t < KK) sQv[t] = q_emb[(size_t)tgt * KK + t];
    __syncthreads();

    {
        const int c = t & 63, kg = t >> 6;
        float acc = 0.f;
#pragma unroll
        for (int j = 0; j < 16; j++)
            acc = fmaf(sQv[kg * 16 + j], __ldg(key_memory + (kg * 16 + j) * CC + c), acc);
        sPart[kg][c] = acc;
    }
    __syncthreads();
    if (t < CC) {
        float s = 0.f;
#pragma unroll
        for (int j = 0; j < 8; j++) s += sPart[j][t];
        sWt[t] = s;
    }
    __syncthreads();
    if (t < 32) {
        float l0 = sWt[t], l1 = sWt[t + 32];
        float mx = fmaxf(l0, l1);
#pragma unroll
        for (int off = 16; off > 0; off >>= 1)
            mx = fmaxf(mx, __shfl_xor_sync(0xffffffffu, mx, off));
        float e0 = __expf(l0 - mx), e1 = __expf(l1 - mx);
        float sm = e0 + e1;
#pragma unroll
        for (int off = 16; off > 0; off >>= 1)
            sm += __shfl_xor_sync(0xffffffffu, sm, off);
        const float inv = 1.f / sm;
        sWt[t] = e0 * inv;
        sWt[t + 32] = e1 * inv;
    }
    __syncthreads();

    {
        const float4 w4 = *(const float4*)(sWt + cg * 4);
        const ull w0 = pack2(w4.x, w4.x), w1 = pack2(w4.y, w4.y);
        const ull w2 = pack2(w4.z, w4.z), w3 = pack2(w4.w, w4.w);
        const ull zero = pack2(0.f, 0.f);
        float r[4];
#pragma unroll
        for (int q = 0; q < 2; q++) {
            ull rv = fma2(m2[q*4+0], w0, fma2(m2[q*4+1], w1,
                     fma2(m2[q*4+2], w2, fma2(m2[q*4+3], w3, zero))));
            float2 f = unpack2(rv);
            r[q*2] = f.x; r[q*2+1] = f.y;
        }
#pragma unroll
        for (int off = 8; off > 0; off >>= 1)
#pragma unroll
            for (int j = 0; j < 4; j++)
                r[j] += __shfl_xor_sync(0xffffffffu, r[j], off);
        if (cg == 0) {
#pragma unroll
            for (int j = 0; j < 4; j++)
                sCat[vg * 4 + j] = r[j];
        }
    }
    if (t < 128) sCat[VV + t] = sQv[t];
    __syncthreads();

    {
        float4 acc4 = make_float4(0.f, 0.f, 0.f, 0.f);
#pragma unroll
        for (int j = 0; j < 16; j++) {
            const int row = wid * 16 + j;
            const float x = sCat[row];
            const float4 wr = *(const float4*)(summ_W + row * SUMD + lane * 4);
            acc4.x = fmaf(x, wr.x, acc4.x);
            acc4.y = fmaf(x, wr.y, acc4.y);
            acc4.z = fmaf(x, wr.z, acc4.z);
            acc4.w = fmaf(x, wr.w, acc4.w);
        }
        *(float4*)&sRed[wid][lane * 4] = acc4;
    }
    __syncthreads();

    if (t < SUMD) {
        float s = 0.f;
#pragma unroll
        for (int j = 0; j < 16; j++) s += sRed[j][t];
        const float sm = tanhf(s + summ_b[t]);
        float p = sm * __ldg(out_W + t);
#pragma unroll
        for (int off = 16; off > 0; off >>= 1)
            p += __shfl_down_sync(0xffffffffu, p, off);
        if (lane == 0) sRed2[wid] = p;
    }
    __syncthreads();
    if (t == 0)
        out[b] = sRed2[0] + sRed2[1] + sRed2[2] + sRed2[3] + out_b[0];
}

// ---------------------------------------------------------------------------
extern "C" void kernel_launch(void* const* d_in, const int* in_sizes, int n_in,
                              void* d_out, int out_size)
{
    const float* q_emb      = (const float*)d_in[0];
    const float* i_emb      = (const float*)d_in[1];
    const float* key_memory = (const float*)d_in[2];
    const float* init_vm    = (const float*)d_in[3];
    const float* erase_W    = (const float*)d_in[4];
    const float* erase_b    = (const float*)d_in[5];
    const float* add_W      = (const float*)d_in[6];
    const float* add_b      = (const float*)d_in[7];
    const float* summ_W     = (const float*)d_in[8];
    const float* summ_b     = (const float*)d_in[9];
    const float* out_W      = (const float*)d_in[10];
    const float* out_b      = (const float*)d_in[11];
    const int*   input      = (const int*)d_in[12];
    const int*   target_id  = (const int*)d_in[13];
    float* out = (float*)d_out;

    cudaFuncSetAttribute(precompute_kernel, cudaFuncAttributeMaxDynamicSharedMemorySize, PRE_SMEM);
    cudaFuncSetAttribute(scan_kernel, cudaFuncAttributeMaxDynamicSharedMemorySize, SCAN_SMEM);

    precompute_kernel<<<NROWS / PROWS, PT, PRE_SMEM>>>(
        q_emb, i_emb, key_memory, erase_W, erase_b, add_W, add_b, input);

    scan_kernel<<<BB, 512, SCAN_SMEM>>>(
        q_emb, key_memory, init_vm, summ_W, summ_b, out_W, out_b, target_id, out);
}

// round 10
// speedup vs baseline: 1.9203x; 1.9203x over previous
#include <cuda_runtime.h>
#include <math.h>
#include <stdint.h>

#define BB 128
#define SS 200
#define QQ 20000
#define VV 128
#define KK 128
#define CC 64
#define SUMD 128
#define NROWS (BB*SS)

// Sliced per-(b,slice,s) record: [negE(32) | A(32) | W(64)] = 128 floats = 512B
#define NSLICE 4
#define SLICEV 32
#define RECF 128
#define RECB (RECF*4)
#define SCAN_SMEM (SS*RECB)          // 102,400 B

// precompute geometry
#define PROWS 64
#define PT 640
#define KCH 16
#define NKCH (KK/KCH)
#define WCH_E (KCH*VV*4)
#define WCH_K (KCH*CC*4)
#define WCH_TOT (2*WCH_E + WCH_K)
#define OFF_QK   (PROWS*KK)
#define OFF_WE   (2*PROWS*KK)
#define OFF_WA   (OFF_WE + 2*KCH*VV)
#define OFF_WK   (OFF_WA + 2*KCH*VV)
#define OFF_MB   (OFF_WK + 2*KCH*CC)
#define PRE_SMEM ((OFF_MB + 4)*4)

__device__ float g_slice[(size_t)BB * NSLICE * SS * RECF];   // 52.4 MB
__device__ float g_mem[(size_t)BB * VV * CC];                // 4 MB

typedef unsigned long long ull;

__device__ __forceinline__ ull fma2(ull a, ull b, ull c) {
    ull d;
    asm("fma.rn.f32x2 %0, %1, %2, %3;" : "=l"(d) : "l"(a), "l"(b), "l"(c));
    return d;
}
__device__ __forceinline__ ull pack2(float x, float y) {
    ull d;
    asm("mov.b64 %0, {%1, %2};" : "=l"(d) : "f"(x), "f"(y));
    return d;
}
__device__ __forceinline__ float2 unpack2(ull v) {
    float2 r;
    asm("mov.b64 {%0, %1}, %2;" : "=f"(r.x), "=f"(r.y) : "l"(v));
    return r;
}
__device__ __forceinline__ uint32_t smem_u32(const void* p) {
    uint32_t a;
    asm("{ .reg .u64 t; cvta.to.shared.u64 t, %1; cvt.u32.u64 %0, t; }" : "=r"(a) : "l"(p));
    return a;
}
__device__ __forceinline__ void mbar_init(uint32_t mbar, uint32_t cnt) {
    asm volatile("mbarrier.init.shared.b64 [%0], %1;" :: "r"(mbar), "r"(cnt) : "memory");
}
__device__ __forceinline__ void mbar_expect_tx(uint32_t mbar, uint32_t bytes) {
    asm volatile("mbarrier.arrive.expect_tx.shared.b64 _, [%0], %1;" :: "r"(mbar), "r"(bytes) : "memory");
}
__device__ __forceinline__ void mbar_wait(uint32_t mbar, uint32_t parity) {
    asm volatile(
        "{\n\t.reg .pred P;\n"
        "WAITLOOP_%=:\n\t"
        "mbarrier.try_wait.parity.acquire.cta.shared::cta.b64 P, [%0], %1, 0x989680;\n\t"
        "@P bra.uni WAITDONE_%=;\n\t"
        "bra.uni WAITLOOP_%=;\n"
        "WAITDONE_%=:\n\t}"
        :: "r"(mbar), "r"(parity) : "memory");
}
__device__ __forceinline__ void bulk_g2s(uint32_t dst, const void* src, uint32_t bytes, uint32_t mbar) {
    asm volatile(
        "cp.async.bulk.shared::cta.global.mbarrier::complete_tx::bytes [%0], [%1], %2, [%3];"
        :: "r"(dst), "l"(src), "r"(bytes), "r"(mbar) : "memory");
}

// ---------------------------------------------------------------------------
// Kernel A: precompute (register-tiled SGEMM, f32x2), writes sliced layout.
// ---------------------------------------------------------------------------
__global__ __launch_bounds__(PT) void precompute_kernel(
    const float* __restrict__ q_emb,
    const float* __restrict__ i_emb,
    const float* __restrict__ key_memory,
    const float* __restrict__ erase_W,
    const float* __restrict__ erase_b,
    const float* __restrict__ add_W,
    const float* __restrict__ add_b,
    const int*   __restrict__ input)
{
    extern __shared__ __align__(16) float psm[];
    float* sIV = psm;
    float* sQK = psm + OFF_QK;
    float* sWE = psm + OFF_WE;
    float* sWA = psm + OFF_WA;
    float* sWK = psm + OFF_WK;
    const uint32_t mb = smem_u32(psm + OFF_MB);

    __shared__ float sLg[PROWS][68];
    __shared__ int   sIdx[PROWS];

    const int t    = threadIdx.x;
    const int lane = t & 31;
    const int wid  = t >> 5;
    const int tc   = t % 80;
    const int tr   = t / 80;
    const int row0 = blockIdx.x * PROWS;

    if (t < PROWS) sIdx[t] = input[row0 + t];
    if (t == 0) {
        mbar_init(mb, 1);
        asm volatile("fence.proxy.async.shared::cta;" ::: "memory");
        mbar_expect_tx(mb, WCH_TOT);
        bulk_g2s(smem_u32(sWE), erase_W,    WCH_E, mb);
        bulk_g2s(smem_u32(sWA), add_W,      WCH_E, mb);
        bulk_g2s(smem_u32(sWK), key_memory, WCH_K, mb);
    }
    __syncthreads();

    for (int r = wid; r < PROWS; r += PT/32) {
        const int idx = sIdx[r];
        const int qid = idx > QQ ? idx - QQ : idx;
        float4 v  = *((const float4*)(i_emb + (size_t)idx * VV) + lane);
        float4 qv = *((const float4*)(q_emb + (size_t)qid * KK) + lane);
        *(float4*)&sIV[r * KK + lane * 4] = v;
        *(float4*)&sQK[r * KK + lane * 4] = qv;
    }
    __syncthreads();

    const float* Asrc = (tc < 64) ? sIV : sQK;
    const float* Wreg;
    int wstride;
    ull bias0, bias1;
    if (tc < 32) {
        Wreg = sWE + tc * 4; wstride = VV;
        float4 b = *(const float4*)(erase_b + tc * 4);
        bias0 = pack2(b.x, b.y); bias1 = pack2(b.z, b.w);
    } else if (tc < 64) {
        Wreg = sWA + (tc - 32) * 4; wstride = VV;
        float4 b = *(const float4*)(add_b + (tc - 32) * 4);
        bias0 = pack2(b.x, b.y); bias1 = pack2(b.z, b.w);
    } else {
        Wreg = sWK + (tc - 64) * 4; wstride = CC;
        bias0 = bias1 = pack2(0.f, 0.f);
    }

    ull acc[8][2];
#pragma unroll
    for (int i = 0; i < 8; i++) { acc[i][0] = bias0; acc[i][1] = bias1; }

    for (int ch = 0; ch < NKCH; ch++) {
        const int buf = ch & 1;
        mbar_wait(mb, ch & 1);
        __syncthreads();
        if (t == 0 && ch + 1 < NKCH) {
            const int nb = buf ^ 1, k0n = (ch + 1) * KCH;
            mbar_expect_tx(mb, WCH_TOT);
            bulk_g2s(smem_u32(sWE + nb * KCH * VV), erase_W    + k0n * VV, WCH_E, mb);
            bulk_g2s(smem_u32(sWA + nb * KCH * VV), add_W      + k0n * VV, WCH_E, mb);
            bulk_g2s(smem_u32(sWK + nb * KCH * CC), key_memory + k0n * CC, WCH_K, mb);
        }

        const float* W = Wreg + buf * KCH * wstride;
        const float* A = Asrc + tr * 8 * KK + ch * KCH;
#pragma unroll
        for (int kk = 0; kk < KCH; kk += 4) {
            ulonglong2 wl[4];
#pragma unroll
            for (int j = 0; j < 4; j++)
                wl[j] = *(const ulonglong2*)(W + (kk + j) * wstride);
            float4 av[8];
#pragma unroll
            for (int i = 0; i < 8; i++)
                av[i] = *(const float4*)(A + i * KK + kk);
#pragma unroll
            for (int j = 0; j < 4; j++) {
#pragma unroll
                for (int i = 0; i < 8; i++) {
                    const float a = ((const float*)&av[i])[j];
                    const ull ad = pack2(a, a);
                    acc[i][0] = fma2(ad, wl[j].x, acc[i][0]);
                    acc[i][1] = fma2(ad, wl[j].y, acc[i][1]);
                }
            }
        }
    }

    // ---- Epilogue: write sliced layout ----
    if (tc < 32) {
        const int sl  = tc >> 3;
        const int off = (tc & 7) * 4;
#pragma unroll
        for (int i = 0; i < 8; i++) {
            const int r = row0 + tr * 8 + i;
            const int b = r / SS, s = r % SS;
            float2 f0 = unpack2(acc[i][0]), f1 = unpack2(acc[i][1]);
            float4 o;
            o.x = -1.f / (1.f + __expf(-f0.x));
            o.y = -1.f / (1.f + __expf(-f0.y));
            o.z = -1.f / (1.f + __expf(-f1.x));
            o.w = -1.f / (1.f + __expf(-f1.y));
            *(float4*)&g_slice[((size_t)(b * NSLICE + sl) * SS + s) * RECF + off] = o;
        }
    } else if (tc < 64) {
        const int c   = tc - 32;
        const int sl  = c >> 3;
        const int off = 32 + (c & 7) * 4;
#pragma unroll
        for (int i = 0; i < 8; i++) {
            const int r = row0 + tr * 8 + i;
            const int b = r / SS, s = r % SS;
            float2 f0 = unpack2(acc[i][0]), f1 = unpack2(acc[i][1]);
            float4 o;
            o.x = tanhf(f0.x); o.y = tanhf(f0.y);
            o.z = tanhf(f1.x); o.w = tanhf(f1.y);
            *(float4*)&g_slice[((size_t)(b * NSLICE + sl) * SS + s) * RECF + off] = o;
        }
    } else {
#pragma unroll
        for (int i = 0; i < 8; i++) {
            float2 f0 = unpack2(acc[i][0]), f1 = unpack2(acc[i][1]);
            float4 o; o.x = f0.x; o.y = f0.y; o.z = f1.x; o.w = f1.y;
            *(float4*)&sLg[tr * 8 + i][(tc - 64) * 4] = o;
        }
    }
    __syncthreads();

    if (t < PROWS) {
        float mx = -1e30f;
#pragma unroll
        for (int c = 0; c < CC; c++) mx = fmaxf(mx, sLg[t][c]);
        float sum = 0.f;
#pragma unroll
        for (int c = 0; c < CC; c++) { float e = __expf(sLg[t][c] - mx); sLg[t][c] = e; sum += e; }
        const float inv = 1.f / sum;
#pragma unroll
        for (int c = 0; c < CC; c++) sLg[t][c] *= inv;
    }
    __syncthreads();

    for (int idx = t; idx < PROWS * (CC / 4); idx += PT) {
        const int r = idx >> 4, q = idx & 15;
        const int gr = row0 + r;
        const int b = gr / SS, s = gr % SS;
        const float4 o = *(const float4*)&sLg[r][q * 4];
#pragma unroll
        for (int j = 0; j < NSLICE; j++)
            *(float4*)&g_slice[((size_t)(b * NSLICE + j) * SS + s) * RECF + 64 + q * 4] = o;
    }
}

// ---------------------------------------------------------------------------
// Kernel B: sliced scan. Grid = BB*NSLICE = 512 CTAs, 256 threads.
// Stage-in: plain coalesced float4 LDG->STS, ONE barrier. Then 200
// barrier-free steps of pure LDS + FMA2.
// ---------------------------------------------------------------------------
__global__ __launch_bounds__(256) void scan_kernel(
    const float* __restrict__ init_value_memory)
{
    extern __shared__ __align__(16) float dsm[];

    const int bs = blockIdx.x;           // b*4 + slice
    const int sl = bs & 3;
    const int b  = bs >> 2;
    const int t  = threadIdx.x;
    const int pg = t >> 4;               // 0..15 v-pair within slice
    const int cg = t & 15;               // 0..15 -> c cols [4*cg, 4*cg+4)

    // stage all 200 steps (102.4 KB): 6400 float4 / 256 threads = 25 each
    {
        const float4* src = (const float4*)(g_slice + (size_t)bs * SS * RECF);
        float4* dst = (float4*)dsm;
#pragma unroll
        for (int i = 0; i < 25; i++)
            dst[t + i * 256] = src[t + i * 256];
    }

    const int v0 = sl * SLICEV + pg * 2;
    ull m2[4];
    {
        const float4 ra = *(const float4*)(init_value_memory + (v0    ) * CC + cg * 4);
        const float4 rb = *(const float4*)(init_value_memory + (v0 + 1) * CC + cg * 4);
        m2[0] = pack2(ra.x, rb.x);
        m2[1] = pack2(ra.y, rb.y);
        m2[2] = pack2(ra.z, rb.z);
        m2[3] = pack2(ra.w, rb.w);
    }
    __syncthreads();

    const float* sp = dsm;
#pragma unroll 4
    for (int s = 0; s < SS; s++, sp += RECF) {
        const ull ne = *(const ull*)(sp + pg * 2);        // (negE[v0], negE[v1])
        const ull aa = *(const ull*)(sp + 32 + pg * 2);   // (A[v0], A[v1])
        const float4 wf = *(const float4*)(sp + 64 + cg * 4);
        const ull w0 = pack2(wf.x, wf.x);
        const ull w1 = pack2(wf.y, wf.y);
        const ull w2 = pack2(wf.z, wf.z);
        const ull w3 = pack2(wf.w, wf.w);
        m2[0] = fma2(w0, fma2(m2[0], ne, aa), m2[0]);
        m2[1] = fma2(w1, fma2(m2[1], ne, aa), m2[1]);
        m2[2] = fma2(w2, fma2(m2[2], ne, aa), m2[2]);
        m2[3] = fma2(w3, fma2(m2[3], ne, aa), m2[3]);
    }

    float* dst0 = g_mem + ((size_t)b * VV + v0) * CC + cg * 4;
    float* dst1 = dst0 + CC;
    float2 f0 = unpack2(m2[0]), f1 = unpack2(m2[1]), f2 = unpack2(m2[2]), f3 = unpack2(m2[3]);
    float4 oa; oa.x = f0.x; oa.y = f1.x; oa.z = f2.x; oa.w = f3.x;
    float4 ob; ob.x = f0.y; ob.y = f1.y; ob.z = f2.y; ob.w = f3.y;
    *(float4*)dst0 = oa;
    *(float4*)dst1 = ob;
}

// ---------------------------------------------------------------------------
// Kernel C: readout. 128 CTAs x 256 threads.
// FIX: sMem rows are 65 floats (260B) -> odd rows are NOT 16B aligned;
// stage with scalar stores (float4 loads from gmem are fine).
// ---------------------------------------------------------------------------
__global__ __launch_bounds__(256) void readout_kernel(
    const float* __restrict__ q_emb,
    const float* __restrict__ key_memory,
    const float* __restrict__ summ_W,
    const float* __restrict__ summ_b,
    const float* __restrict__ out_W,
    const float* __restrict__ out_b,
    const int*   __restrict__ target_id,
    float* __restrict__ out)
{
    __shared__ float sMem[VV][CC + 1];
    __shared__ float sQv[KK];
    __shared__ float sWt[CC];
    __shared__ float sCat[VV + KK];
    __shared__ float sPart[4][CC + 1];
    __shared__ float sRed[8][SUMD + 4];
    __shared__ float sRed2[4];

    const int b    = blockIdx.x;
    const int t    = threadIdx.x;
    const int lane = t & 31;
    const int wid  = t >> 5;

    const float* gm = g_mem + (size_t)b * VV * CC;
#pragma unroll
    for (int i = 0; i < 8; i++) {
        const int idx = t + i * 256;          // float4 index
        const int v = idx >> 4, q = idx & 15;
        const float4 val = *(const float4*)(gm + v * CC + q * 4);
        sMem[v][q * 4 + 0] = val.x;           // scalar STS: row stride 260B
        sMem[v][q * 4 + 1] = val.y;
        sMem[v][q * 4 + 2] = val.z;
        sMem[v][q * 4 + 3] = val.w;
    }
    if (t < KK) sQv[t] = q_emb[(size_t)target_id[b] * KK + t];
    __syncthreads();

    {
        const int c = t & 63, kg = t >> 6;
        float acc = 0.f;
#pragma unroll
        for (int j = 0; j < 32; j++)
            acc = fmaf(sQv[kg * 32 + j], __ldg(key_memory + (kg * 32 + j) * CC + c), acc);
        sPart[kg][c] = acc;
    }
    __syncthreads();
    if (t < CC) {
        float s = 0.f;
#pragma unroll
        for (int j = 0; j < 4; j++) s += sPart[j][t];
        sWt[t] = s;
    }
    __syncthreads();
    if (t < 32) {
        float l0 = sWt[t], l1 = sWt[t + 32];
        float mx = fmaxf(l0, l1);
#pragma unroll
        for (int off = 16; off > 0; off >>= 1)
            mx = fmaxf(mx, __shfl_xor_sync(0xffffffffu, mx, off));
        float e0 = __expf(l0 - mx), e1 = __expf(l1 - mx);
        float sm = e0 + e1;
#pragma unroll
        for (int off = 16; off > 0; off >>= 1)
            sm += __shfl_xor_sync(0xffffffffu, sm, off);
        const float inv = 1.f / sm;
        sWt[t] = e0 * inv;
        sWt[t + 32] = e1 * inv;
    }
    __syncthreads();

    if (t < VV) {
        float acc = 0.f;
#pragma unroll
        for (int c = 0; c < CC; c++)
            acc = fmaf(sMem[t][c], sWt[c], acc);
        sCat[t] = acc;
    } else {
        sCat[t] = sQv[t - 128];
    }
    __syncthreads();

    {
        float4 acc4 = make_float4(0.f, 0.f, 0.f, 0.f);
#pragma unroll
        for (int j = 0; j < 32; j++) {
            const int row = wid * 32 + j;
            const float x = sCat[row];
            const float4 wr = *(const float4*)(summ_W + row * SUMD + lane * 4);
            acc4.x = fmaf(x, wr.x, acc4.x);
            acc4.y = fmaf(x, wr.y, acc4.y);
            acc4.z = fmaf(x, wr.z, acc4.z);
            acc4.w = fmaf(x, wr.w, acc4.w);
        }
        *(float4*)&sRed[wid][lane * 4] = acc4;
    }
    __syncthreads();

    if (t < SUMD) {
        float s = 0.f;
#pragma unroll
        for (int j = 0; j < 8; j++) s += sRed[j][t];
        const float sm = tanhf(s + summ_b[t]);
        float p = sm * __ldg(out_W + t);
#pragma unroll
        for (int off = 16; off > 0; off >>= 1)
            p += __shfl_down_sync(0xffffffffu, p, off);
        if (lane == 0) sRed2[wid] = p;
    }
    __syncthreads();
    if (t == 0)
        out[b] = sRed2[0] + sRed2[1] + sRed2[2] + sRed2[3] + out_b[0];
}

// ---------------------------------------------------------------------------
extern "C" void kernel_launch(void* const* d_in, const int* in_sizes, int n_in,
                              void* d_out, int out_size)
{
    const float* q_emb      = (const float*)d_in[0];
    const float* i_emb      = (const float*)d_in[1];
    const float* key_memory = (const float*)d_in[2];
    const float* init_vm    = (const float*)d_in[3];
    const float* erase_W    = (const float*)d_in[4];
    const float* erase_b    = (const float*)d_in[5];
    const float* add_W      = (const float*)d_in[6];
    const float* add_b      = (const float*)d_in[7];
    const float* summ_W     = (const float*)d_in[8];
    const float* summ_b     = (const float*)d_in[9];
    const float* out_W      = (const float*)d_in[10];
    const float* out_b      = (const float*)d_in[11];
    const int*   input      = (const int*)d_in[12];
    const int*   target_id  = (const int*)d_in[13];
    float* out = (float*)d_out;

    cudaFuncSetAttribute(precompute_kernel, cudaFuncAttributeMaxDynamicSharedMemorySize, PRE_SMEM);
    cudaFuncSetAttribute(scan_kernel, cudaFuncAttributeMaxDynamicSharedMemorySize, SCAN_SMEM);

    precompute_kernel<<<NROWS / PROWS, PT, PRE_SMEM>>>(
        q_emb, i_emb, key_memory, erase_W, erase_b, add_W, add_b, input);

    scan_kernel<<<BB * NSLICE, 256, SCAN_SMEM>>>(init_vm);

    readout_kernel<<<BB, 256>>>(
        q_emb, key_memory, summ_W, summ_b, out_W, out_b, target_id, out);
}